// round 15
// baseline (speedup 1.0000x reference)
#include <cuda_runtime.h>
#include <cuda_fp16.h>
#include <mma.h>
#include <stdint.h>

using namespace nvcuda;

#define N_NODES 100000
#define N_EDGES 3200000
#define D 128
#define LN_EPS 1e-5f

// ---------------------------------------------------------------------------
// Device-global scratch (no allocations allowed).
// ---------------------------------------------------------------------------
__device__ __half g_Hh[(size_t)N_NODES * D];   // LN(X) @ W^T + b, fp16
__device__ int   g_off[N_NODES + 1];           // CSR offsets (by dst)
__device__ int   g_rank[N_EDGES];              // within-bucket rank (from hist)
__device__ int2  g_sw[N_EDGES];                // packed (src, w_bits) sorted by dst
__device__ int   g_bsum[128];                  // scan block sums

// ---------------------------------------------------------------------------
// Host-side overlap context (host resources only; created once).
// ---------------------------------------------------------------------------
struct OverlapCtx {
    cudaStream_t s2;
    cudaEvent_t  e_fork, e_join;
    OverlapCtx() {
        cudaStreamCreateWithFlags(&s2, cudaStreamNonBlocking);
        cudaEventCreateWithFlags(&e_fork, cudaEventDisableTiming);
        cudaEventCreateWithFlags(&e_join, cudaEventDisableTiming);
    }
};
static OverlapCtx g_ctx;

// ===========================================================================
// Kernel A: edge histogram + per-edge rank capture (atomic return value).
// ===========================================================================
#define HIST_BLOCKS 512
__global__ void __launch_bounds__(256)
hist_rank_kernel(const int* __restrict__ edst, int E) {
    const int n4     = E >> 2;
    const int4* p    = reinterpret_cast<const int4*>(edst);
    int4* rk         = reinterpret_cast<int4*>(g_rank);
    const int stride = HIST_BLOCKS * 256;
    const int gid    = blockIdx.x * 256 + threadIdx.x;
    for (int i = gid; i < n4; i += stride) {
        const int4 v = __ldcs(&p[i]);
        int4 r;
        r.x = atomicAdd(&g_off[v.x + 1], 1);
        r.y = atomicAdd(&g_off[v.y + 1], 1);
        r.z = atomicAdd(&g_off[v.z + 1], 1);
        r.w = atomicAdd(&g_off[v.w + 1], 1);
        rk[i] = r;                                 // coalesced int4 store
    }
    for (int e = (n4 << 2) + gid; e < E; e += stride)      // tail
        g_rank[e] = atomicAdd(&g_off[edst[e] + 1], 1);
}

// ===========================================================================
// Scan: chunk-scan + fused (bsum-prefix + add)
// ===========================================================================
__device__ __forceinline__ int warp_incl_scan(int v, int lane) {
    #pragma unroll
    for (int off = 1; off < 32; off <<= 1) {
        int t = __shfl_up_sync(0xffffffffu, v, off);
        if (lane >= off) v += t;
    }
    return v;
}

__global__ void scan_chunk_kernel(int n) {        // blockDim = 1024
    __shared__ int wsum[32];
    const int tid  = threadIdx.x;
    const int lane = tid & 31;
    const int wid  = tid >> 5;
    const int gi   = blockIdx.x * 1024 + tid;
    int v = (gi < n) ? g_off[gi] : 0;
    v = warp_incl_scan(v, lane);
    if (lane == 31) wsum[wid] = v;
    __syncthreads();
    if (wid == 0) wsum[lane] = warp_incl_scan(wsum[lane], lane);
    __syncthreads();
    if (wid > 0) v += wsum[wid - 1];
    if (gi < n) g_off[gi] = v;
    if (tid == 1023) g_bsum[blockIdx.x] = v;
}

__global__ void scan_add_fused_kernel(int n, int nb) {   // blockDim = 1024
    __shared__ int bs[128];
    const int tid = threadIdx.x;
    if (tid < nb) bs[tid] = g_bsum[tid];
    __syncthreads();
    if (tid == 0) {
        int run = 0;
        for (int i = 0; i < nb; ++i) { run += bs[i]; bs[i] = run; }
    }
    __syncthreads();
    const int gi = blockIdx.x * 1024 + tid;
    if (gi >= n) return;
    const int add = (blockIdx.x > 0) ? bs[blockIdx.x - 1] : 0;
    g_off[gi] = g_off[gi] + add;
}

// ===========================================================================
// Kernel C: atomic-free edge reorder: pos = g_off[dst] + rank[e].
// ===========================================================================
#define RORD_BLOCKS 1024
__global__ void __launch_bounds__(256)
reorder_kernel(const int* __restrict__ esrc,
               const int* __restrict__ edst,
               const float* __restrict__ ew, int E) {
    const int n4     = E >> 2;
    const int4*   pd = reinterpret_cast<const int4*>(edst);
    const int4*   ps = reinterpret_cast<const int4*>(esrc);
    const float4* pw = reinterpret_cast<const float4*>(ew);
    const int4*   pr = reinterpret_cast<const int4*>(g_rank);
    const int stride = RORD_BLOCKS * 256;
    const int gid    = blockIdx.x * 256 + threadIdx.x;
    for (int i = gid; i < n4; i += stride) {
        const int4   d = __ldcs(&pd[i]);
        const int4   s = __ldcs(&ps[i]);
        const float4 w = __ldcs(&pw[i]);
        const int4   r = __ldcs(&pr[i]);
        g_sw[g_off[d.x] + r.x] = make_int2(s.x, __float_as_int(w.x));
        g_sw[g_off[d.y] + r.y] = make_int2(s.y, __float_as_int(w.y));
        g_sw[g_off[d.z] + r.z] = make_int2(s.z, __float_as_int(w.z));
        g_sw[g_off[d.w] + r.w] = make_int2(s.w, __float_as_int(w.w));
    }
    for (int e = (n4 << 2) + gid; e < E; e += stride)      // tail
        g_sw[g_off[__ldcs(&edst[e])] + g_rank[e]] =
            make_int2(__ldcs(&esrc[e]), __float_as_int(__ldcs(&ew[e])));
}

// ===========================================================================
// Kernel D: fused LayerNorm + Linear (X -> g_Hh), fp16 tensor-core GEMM.
//   64 rows/block, 256 threads (8 warps).
// ===========================================================================
#define ROWS_PB 64
#define W_LD 136
#define XN_LD 136
#define WH_HALFS (128 * W_LD)
#define XN_HALFS (ROWS_PB * XN_LD)
#define STAGE_OFF_B ((WH_HALFS + XN_HALFS) * 2)
#define SMEM_BYTES (STAGE_OFF_B + 8 * 256 * 4)

__global__ void __launch_bounds__(256, 2)
ln_linear_kernel(const float* __restrict__ X,
                 const float* __restrict__ gamma,
                 const float* __restrict__ beta,
                 const float* __restrict__ W,
                 const float* __restrict__ bias) {
    extern __shared__ char smem[];
    __half* Wh = reinterpret_cast<__half*>(smem);              // [128][136]
    __half* Xn = Wh + WH_HALFS;                                // [64][136]
    float* stage = reinterpret_cast<float*>(smem + STAGE_OFF_B);

    const int tid  = threadIdx.x;
    const int lane = tid & 31;
    const int warp = tid >> 5;
    const int row0 = blockIdx.x * ROWS_PB;

    // ---- W -> fp16 smem ----
    {
        const float4* W4 = reinterpret_cast<const float4*>(W);
        for (int i = tid; i < 128 * 32; i += 256) {
            const int o  = i >> 5;
            const int d4 = (i & 31) << 2;
            const float4 w = W4[i];
            const __half2 p0 = __floats2half2_rn(w.x, w.y);
            const __half2 p1 = __floats2half2_rn(w.z, w.w);
            uint2 st;
            st.x = *reinterpret_cast<const unsigned*>(&p0);
            st.y = *reinterpret_cast<const unsigned*>(&p1);
            *reinterpret_cast<uint2*>(Wh + o * W_LD + d4) = st;
        }
    }

    // ---- LayerNorm: 8 warps x 8 rows; fp16 rows into Xn ----
    #pragma unroll
    for (int rr = 0; rr < ROWS_PB / 8; ++rr) {
        const int r   = warp + rr * 8;
        const int row = row0 + r;
        float4 v = make_float4(0.f, 0.f, 0.f, 0.f);
        if (row < N_NODES)
            v = reinterpret_cast<const float4*>(X + (size_t)row * D)[lane];
        float s  = v.x + v.y + v.z + v.w;
        float sq = v.x * v.x + v.y * v.y + v.z * v.z + v.w * v.w;
        #pragma unroll
        for (int off = 16; off; off >>= 1) {
            s  += __shfl_xor_sync(0xffffffffu, s,  off);
            sq += __shfl_xor_sync(0xffffffffu, sq, off);
        }
        const float mu  = s * (1.0f / D);
        const float var = sq * (1.0f / D) - mu * mu;
        const float inv = rsqrtf(var + LN_EPS);
        const float4 g  = reinterpret_cast<const float4*>(gamma)[lane];
        const float4 be = reinterpret_cast<const float4*>(beta)[lane];
        const float h0 = (v.x - mu) * inv * g.x + be.x;
        const float h1 = (v.y - mu) * inv * g.y + be.y;
        const float h2 = (v.z - mu) * inv * g.z + be.z;
        const float h3 = (v.w - mu) * inv * g.w + be.w;
        const __half2 p0 = __floats2half2_rn(h0, h1);
        const __half2 p1 = __floats2half2_rn(h2, h3);
        uint2 st;
        st.x = *reinterpret_cast<const unsigned*>(&p0);
        st.y = *reinterpret_cast<const unsigned*>(&p1);
        *reinterpret_cast<uint2*>(Xn + r * XN_LD + (lane << 2)) = st;
    }
    __syncthreads();

    // ---- tensor-core GEMM: H = Xn @ W^T ----
    const int r16 = warp >> 1;
    const int cb  = (warp & 1) * 64;

    wmma::fragment<wmma::accumulator, 16, 16, 16, float> c[4];
    #pragma unroll
    for (int ct = 0; ct < 4; ++ct) wmma::fill_fragment(c[ct], 0.0f);

    #pragma unroll
    for (int k0 = 0; k0 < 8; ++k0) {
        wmma::fragment<wmma::matrix_a, 16, 16, 16, __half, wmma::row_major> a;
        wmma::load_matrix_sync(a, Xn + r16 * 16 * XN_LD + k0 * 16, XN_LD);
        #pragma unroll
        for (int ct = 0; ct < 4; ++ct) {
            wmma::fragment<wmma::matrix_b, 16, 16, 16, __half, wmma::col_major> b;
            wmma::load_matrix_sync(b, Wh + (cb + ct * 16) * W_LD + k0 * 16, W_LD);
            wmma::mma_sync(c[ct], a, b, c[ct]);
        }
    }

    // ---- epilogue: +bias, fp16, store ----
    float* st = stage + warp * 256;
    const int rt = lane >> 1;
    const int ch = (lane & 1) * 8;
    #pragma unroll
    for (int ct = 0; ct < 4; ++ct) {
        wmma::store_matrix_sync(st, c[ct], 16, wmma::mem_row_major);
        __syncwarp();
        const int grow = row0 + r16 * 16 + rt;
        if (grow < N_NODES) {
            const int gcol = cb + ct * 16 + ch;
            float v[8];
            #pragma unroll
            for (int j = 0; j < 8; ++j)
                v[j] = st[rt * 16 + ch + j] + __ldg(&bias[gcol + j]);
            const __half2 q0 = __floats2half2_rn(v[0], v[1]);
            const __half2 q1 = __floats2half2_rn(v[2], v[3]);
            const __half2 q2 = __floats2half2_rn(v[4], v[5]);
            const __half2 q3 = __floats2half2_rn(v[6], v[7]);
            uint4 pkt;
            pkt.x = *reinterpret_cast<const unsigned*>(&q0);
            pkt.y = *reinterpret_cast<const unsigned*>(&q1);
            pkt.z = *reinterpret_cast<const unsigned*>(&q2);
            pkt.w = *reinterpret_cast<const unsigned*>(&q3);
            *reinterpret_cast<uint4*>(g_Hh + (size_t)grow * D + gcol) = pkt;
        }
        __syncwarp();
    }
}

// ===========================================================================
// Kernel E: aggregate. One warp per dst node, unroll-4 front-batched gathers.
//   out = relu(sum w*H[src]) + X.
// ===========================================================================
__device__ __forceinline__ void fma_h4(float4& acc, uint2 raw, float w) {
    const __half2 a = *reinterpret_cast<const __half2*>(&raw.x);
    const __half2 b = *reinterpret_cast<const __half2*>(&raw.y);
    const float2 f01 = __half22float2(a);
    const float2 f23 = __half22float2(b);
    acc.x = fmaf(w, f01.x, acc.x);
    acc.y = fmaf(w, f01.y, acc.y);
    acc.z = fmaf(w, f23.x, acc.z);
    acc.w = fmaf(w, f23.y, acc.w);
}

__global__ void __launch_bounds__(256)
aggregate_kernel(const float* __restrict__ X, float* __restrict__ out) {
    const int gw = (blockIdx.x * blockDim.x + threadIdx.x) >> 5;
    if (gw >= N_NODES) return;
    const int lane = threadIdx.x & 31;

    const int beg = g_off[gw];
    const int end = g_off[gw + 1];

    float4 acc = make_float4(0.f, 0.f, 0.f, 0.f);
    int e = beg;

    for (; e + 3 < end; e += 4) {
        const int2 sw0 = __ldcs(&g_sw[e]);
        const int2 sw1 = __ldcs(&g_sw[e + 1]);
        const int2 sw2 = __ldcs(&g_sw[e + 2]);
        const int2 sw3 = __ldcs(&g_sw[e + 3]);
        const uint2 r0 = __ldg(
            reinterpret_cast<const uint2*>(g_Hh + (size_t)sw0.x * D) + lane);
        const uint2 r1 = __ldg(
            reinterpret_cast<const uint2*>(g_Hh + (size_t)sw1.x * D) + lane);
        const uint2 r2 = __ldg(
            reinterpret_cast<const uint2*>(g_Hh + (size_t)sw2.x * D) + lane);
        const uint2 r3 = __ldg(
            reinterpret_cast<const uint2*>(g_Hh + (size_t)sw3.x * D) + lane);
        fma_h4(acc, r0, __int_as_float(sw0.y));
        fma_h4(acc, r1, __int_as_float(sw1.y));
        fma_h4(acc, r2, __int_as_float(sw2.y));
        fma_h4(acc, r3, __int_as_float(sw3.y));
    }
    for (; e < end; ++e) {
        const int2 sw = __ldcs(&g_sw[e]);
        const uint2 r = __ldg(
            reinterpret_cast<const uint2*>(g_Hh + (size_t)sw.x * D) + lane);
        fma_h4(acc, r, __int_as_float(sw.y));
    }

    const float4 xv =
        __ldcs(reinterpret_cast<const float4*>(X + (size_t)gw * D) + lane);
    float4 o;
    o.x = fmaxf(acc.x, 0.f) + xv.x;
    o.y = fmaxf(acc.y, 0.f) + xv.y;
    o.z = fmaxf(acc.z, 0.f) + xv.z;
    o.w = fmaxf(acc.w, 0.f) + xv.w;
    __stcs(reinterpret_cast<float4*>(out + (size_t)gw * D) + lane, o);
}

// ===========================================================================
extern "C" void kernel_launch(void* const* d_in, const int* in_sizes, int n_in,
                              void* d_out, int out_size) {
    const float* X     = (const float*)d_in[0];
    const int*   esrc  = (const int*)d_in[1];
    const int*   edst  = (const int*)d_in[2];
    const float* ew    = (const float*)d_in[3];
    const float* gamma = (const float*)d_in[4];
    const float* beta  = (const float*)d_in[5];
    const float* W     = (const float*)d_in[6];
    const float* bias  = (const float*)d_in[7];
    float* out         = (float*)d_out;
    const int E        = in_sizes[1];

    cudaFuncSetAttribute(ln_linear_kernel,
                         cudaFuncAttributeMaxDynamicSharedMemorySize,
                         SMEM_BYTES);

    void* off_ptr = nullptr;
    cudaGetSymbolAddress(&off_ptr, g_off);

    const int n  = N_NODES + 1;
    const int nb = (n + 1023) / 1024;                 // 98

    // --- fork: CSR chain on side stream, GEMM on main stream ---------------
    cudaEventRecord(g_ctx.e_fork, 0);
    cudaStreamWaitEvent(g_ctx.s2, g_ctx.e_fork, 0);

    cudaMemsetAsync(off_ptr, 0, n * sizeof(int), g_ctx.s2);
    hist_rank_kernel<<<HIST_BLOCKS, 256, 0, g_ctx.s2>>>(edst, E);
    scan_chunk_kernel<<<nb, 1024, 0, g_ctx.s2>>>(n);
    scan_add_fused_kernel<<<nb, 1024, 0, g_ctx.s2>>>(n, nb);
    reorder_kernel<<<RORD_BLOCKS, 256, 0, g_ctx.s2>>>(esrc, edst, ew, E);
    cudaEventRecord(g_ctx.e_join, g_ctx.s2);

    ln_linear_kernel<<<(N_NODES + ROWS_PB - 1) / ROWS_PB, 256, SMEM_BYTES>>>(
        X, gamma, beta, W, bias);

    // --- join ------------------------------------------------------------
    cudaStreamWaitEvent(0, g_ctx.e_join, 0);
    aggregate_kernel<<<(N_NODES * 32 + 255) / 256, 256>>>(X, out);
}

// round 16
// speedup vs baseline: 1.0525x; 1.0525x over previous
#include <cuda_runtime.h>
#include <cuda_fp16.h>
#include <mma.h>
#include <stdint.h>

using namespace nvcuda;

#define N_NODES 100000
#define N_EDGES 3200000
#define D 128
#define LN_EPS 1e-5f

// ---------------------------------------------------------------------------
// Device-global scratch (no allocations allowed).
// ---------------------------------------------------------------------------
__device__ __half   g_Hh[(size_t)N_NODES * D]; // LN(X) @ W^T + b, fp16
__device__ int      g_off[N_NODES + 1];        // CSR offsets (by dst)
__device__ int      g_rank[N_EDGES];           // within-bucket rank (from hist)
__device__ unsigned g_swp[N_EDGES];            // packed (src<<15 | fp16(w))
__device__ int      g_bsum[128];               // scan block sums

// ---------------------------------------------------------------------------
// Host-side overlap context (host resources only; created once).
// ---------------------------------------------------------------------------
struct OverlapCtx {
    cudaStream_t s2;
    cudaEvent_t  e_fork, e_join;
    OverlapCtx() {
        cudaStreamCreateWithFlags(&s2, cudaStreamNonBlocking);
        cudaEventCreateWithFlags(&e_fork, cudaEventDisableTiming);
        cudaEventCreateWithFlags(&e_join, cudaEventDisableTiming);
    }
};
static OverlapCtx g_ctx;

// ===========================================================================
// Kernel A: edge histogram + per-edge rank capture (atomic return value).
// ===========================================================================
#define HIST_BLOCKS 512
__global__ void __launch_bounds__(256)
hist_rank_kernel(const int* __restrict__ edst, int E) {
    const int n4     = E >> 2;
    const int4* p    = reinterpret_cast<const int4*>(edst);
    int4* rk         = reinterpret_cast<int4*>(g_rank);
    const int stride = HIST_BLOCKS * 256;
    const int gid    = blockIdx.x * 256 + threadIdx.x;
    for (int i = gid; i < n4; i += stride) {
        const int4 v = __ldcs(&p[i]);
        int4 r;
        r.x = atomicAdd(&g_off[v.x + 1], 1);
        r.y = atomicAdd(&g_off[v.y + 1], 1);
        r.z = atomicAdd(&g_off[v.z + 1], 1);
        r.w = atomicAdd(&g_off[v.w + 1], 1);
        rk[i] = r;
    }
    for (int e = (n4 << 2) + gid; e < E; e += stride)      // tail
        g_rank[e] = atomicAdd(&g_off[edst[e] + 1], 1);
}

// ===========================================================================
// Scan: chunk-scan + fused (bsum-prefix + add)
// ===========================================================================
__device__ __forceinline__ int warp_incl_scan(int v, int lane) {
    #pragma unroll
    for (int off = 1; off < 32; off <<= 1) {
        int t = __shfl_up_sync(0xffffffffu, v, off);
        if (lane >= off) v += t;
    }
    return v;
}

__global__ void scan_chunk_kernel(int n) {        // blockDim = 1024
    __shared__ int wsum[32];
    const int tid  = threadIdx.x;
    const int lane = tid & 31;
    const int wid  = tid >> 5;
    const int gi   = blockIdx.x * 1024 + tid;
    int v = (gi < n) ? g_off[gi] : 0;
    v = warp_incl_scan(v, lane);
    if (lane == 31) wsum[wid] = v;
    __syncthreads();
    if (wid == 0) wsum[lane] = warp_incl_scan(wsum[lane], lane);
    __syncthreads();
    if (wid > 0) v += wsum[wid - 1];
    if (gi < n) g_off[gi] = v;
    if (tid == 1023) g_bsum[blockIdx.x] = v;
}

__global__ void scan_add_fused_kernel(int n, int nb) {   // blockDim = 1024
    __shared__ int bs[128];
    const int tid = threadIdx.x;
    if (tid < nb) bs[tid] = g_bsum[tid];
    __syncthreads();
    if (tid == 0) {
        int run = 0;
        for (int i = 0; i < nb; ++i) { run += bs[i]; bs[i] = run; }
    }
    __syncthreads();
    const int gi = blockIdx.x * 1024 + tid;
    if (gi >= n) return;
    const int add = (blockIdx.x > 0) ? bs[blockIdx.x - 1] : 0;
    g_off[gi] = g_off[gi] + add;
}

// ===========================================================================
// Kernel C: atomic-free reorder, 4-byte packed payload.
//   pos = g_off[dst] + rank[e];  g_swp[pos] = (src<<15) | fp16bits(w).
// ===========================================================================
#define RORD_BLOCKS 1024
__device__ __forceinline__ unsigned pack_sw(int src, float w) {
    const unsigned hb = (unsigned)__half_as_ushort(__float2half_rn(w)) & 0x7fffu;
    return ((unsigned)src << 15) | hb;
}

__global__ void __launch_bounds__(256)
reorder_kernel(const int* __restrict__ esrc,
               const int* __restrict__ edst,
               const float* __restrict__ ew, int E) {
    const int n4     = E >> 2;
    const int4*   pd = reinterpret_cast<const int4*>(edst);
    const int4*   ps = reinterpret_cast<const int4*>(esrc);
    const float4* pw = reinterpret_cast<const float4*>(ew);
    const int4*   pr = reinterpret_cast<const int4*>(g_rank);
    const int stride = RORD_BLOCKS * 256;
    const int gid    = blockIdx.x * 256 + threadIdx.x;
    for (int i = gid; i < n4; i += stride) {
        const int4   d = __ldcs(&pd[i]);
        const int4   s = __ldcs(&ps[i]);
        const float4 w = __ldcs(&pw[i]);
        const int4   r = __ldcs(&pr[i]);
        g_swp[g_off[d.x] + r.x] = pack_sw(s.x, w.x);
        g_swp[g_off[d.y] + r.y] = pack_sw(s.y, w.y);
        g_swp[g_off[d.z] + r.z] = pack_sw(s.z, w.z);
        g_swp[g_off[d.w] + r.w] = pack_sw(s.w, w.w);
    }
    for (int e = (n4 << 2) + gid; e < E; e += stride)      // tail
        g_swp[g_off[__ldcs(&edst[e])] + g_rank[e]] =
            pack_sw(__ldcs(&esrc[e]), __ldcs(&ew[e]));
}

// ===========================================================================
// Kernel D: fused LayerNorm + Linear (X -> g_Hh), fp16 tensor-core GEMM.
// ===========================================================================
#define ROWS_PB 64
#define W_LD 136
#define XN_LD 136
#define WH_HALFS (128 * W_LD)
#define XN_HALFS (ROWS_PB * XN_LD)
#define STAGE_OFF_B ((WH_HALFS + XN_HALFS) * 2)
#define SMEM_BYTES (STAGE_OFF_B + 8 * 256 * 4)

__global__ void __launch_bounds__(256, 2)
ln_linear_kernel(const float* __restrict__ X,
                 const float* __restrict__ gamma,
                 const float* __restrict__ beta,
                 const float* __restrict__ W,
                 const float* __restrict__ bias) {
    extern __shared__ char smem[];
    __half* Wh = reinterpret_cast<__half*>(smem);              // [128][136]
    __half* Xn = Wh + WH_HALFS;                                // [64][136]
    float* stage = reinterpret_cast<float*>(smem + STAGE_OFF_B);

    const int tid  = threadIdx.x;
    const int lane = tid & 31;
    const int warp = tid >> 5;
    const int row0 = blockIdx.x * ROWS_PB;

    // ---- W -> fp16 smem ----
    {
        const float4* W4 = reinterpret_cast<const float4*>(W);
        for (int i = tid; i < 128 * 32; i += 256) {
            const int o  = i >> 5;
            const int d4 = (i & 31) << 2;
            const float4 w = W4[i];
            const __half2 p0 = __floats2half2_rn(w.x, w.y);
            const __half2 p1 = __floats2half2_rn(w.z, w.w);
            uint2 st;
            st.x = *reinterpret_cast<const unsigned*>(&p0);
            st.y = *reinterpret_cast<const unsigned*>(&p1);
            *reinterpret_cast<uint2*>(Wh + o * W_LD + d4) = st;
        }
    }

    // ---- LayerNorm: 8 warps x 8 rows; fp16 rows into Xn ----
    #pragma unroll
    for (int rr = 0; rr < ROWS_PB / 8; ++rr) {
        const int r   = warp + rr * 8;
        const int row = row0 + r;
        float4 v = make_float4(0.f, 0.f, 0.f, 0.f);
        if (row < N_NODES)
            v = reinterpret_cast<const float4*>(X + (size_t)row * D)[lane];
        float s  = v.x + v.y + v.z + v.w;
        float sq = v.x * v.x + v.y * v.y + v.z * v.z + v.w * v.w;
        #pragma unroll
        for (int off = 16; off; off >>= 1) {
            s  += __shfl_xor_sync(0xffffffffu, s,  off);
            sq += __shfl_xor_sync(0xffffffffu, sq, off);
        }
        const float mu  = s * (1.0f / D);
        const float var = sq * (1.0f / D) - mu * mu;
        const float inv = rsqrtf(var + LN_EPS);
        const float4 g  = reinterpret_cast<const float4*>(gamma)[lane];
        const float4 be = reinterpret_cast<const float4*>(beta)[lane];
        const float h0 = (v.x - mu) * inv * g.x + be.x;
        const float h1 = (v.y - mu) * inv * g.y + be.y;
        const float h2 = (v.z - mu) * inv * g.z + be.z;
        const float h3 = (v.w - mu) * inv * g.w + be.w;
        const __half2 p0 = __floats2half2_rn(h0, h1);
        const __half2 p1 = __floats2half2_rn(h2, h3);
        uint2 st;
        st.x = *reinterpret_cast<const unsigned*>(&p0);
        st.y = *reinterpret_cast<const unsigned*>(&p1);
        *reinterpret_cast<uint2*>(Xn + r * XN_LD + (lane << 2)) = st;
    }
    __syncthreads();

    // ---- tensor-core GEMM: H = Xn @ W^T ----
    const int r16 = warp >> 1;
    const int cb  = (warp & 1) * 64;

    wmma::fragment<wmma::accumulator, 16, 16, 16, float> c[4];
    #pragma unroll
    for (int ct = 0; ct < 4; ++ct) wmma::fill_fragment(c[ct], 0.0f);

    #pragma unroll
    for (int k0 = 0; k0 < 8; ++k0) {
        wmma::fragment<wmma::matrix_a, 16, 16, 16, __half, wmma::row_major> a;
        wmma::load_matrix_sync(a, Xn + r16 * 16 * XN_LD + k0 * 16, XN_LD);
        #pragma unroll
        for (int ct = 0; ct < 4; ++ct) {
            wmma::fragment<wmma::matrix_b, 16, 16, 16, __half, wmma::col_major> b;
            wmma::load_matrix_sync(b, Wh + (cb + ct * 16) * W_LD + k0 * 16, W_LD);
            wmma::mma_sync(c[ct], a, b, c[ct]);
        }
    }

    // ---- epilogue: +bias, fp16, store ----
    float* st = stage + warp * 256;
    const int rt = lane >> 1;
    const int ch = (lane & 1) * 8;
    #pragma unroll
    for (int ct = 0; ct < 4; ++ct) {
        wmma::store_matrix_sync(st, c[ct], 16, wmma::mem_row_major);
        __syncwarp();
        const int grow = row0 + r16 * 16 + rt;
        if (grow < N_NODES) {
            const int gcol = cb + ct * 16 + ch;
            float v[8];
            #pragma unroll
            for (int j = 0; j < 8; ++j)
                v[j] = st[rt * 16 + ch + j] + __ldg(&bias[gcol + j]);
            const __half2 q0 = __floats2half2_rn(v[0], v[1]);
            const __half2 q1 = __floats2half2_rn(v[2], v[3]);
            const __half2 q2 = __floats2half2_rn(v[4], v[5]);
            const __half2 q3 = __floats2half2_rn(v[6], v[7]);
            uint4 pkt;
            pkt.x = *reinterpret_cast<const unsigned*>(&q0);
            pkt.y = *reinterpret_cast<const unsigned*>(&q1);
            pkt.z = *reinterpret_cast<const unsigned*>(&q2);
            pkt.w = *reinterpret_cast<const unsigned*>(&q3);
            *reinterpret_cast<uint4*>(g_Hh + (size_t)grow * D + gcol) = pkt;
        }
        __syncwarp();
    }
}

// ===========================================================================
// Kernel E: aggregate. One warp per node; TWO edges of the SAME node per
// iteration (lanes 0-15 even edges, 16-31 odd edges; lane loads uint4=16B).
// Combine halves with shfl_xor(16). out = relu(sum w*H[src]) + X.
// ===========================================================================
__device__ __forceinline__ float unpack_w(unsigned v) {
    __half_raw hr;
    hr.x = (unsigned short)(v & 0x7fffu);
    return __half2float(*reinterpret_cast<__half*>(&hr));
}

__device__ __forceinline__ void fma_h8(float* acc, uint4 raw, float w) {
    const __half2* hp = reinterpret_cast<const __half2*>(&raw);
    #pragma unroll
    for (int k = 0; k < 4; ++k) {
        const float2 f = __half22float2(hp[k]);
        acc[2 * k + 0] = fmaf(w, f.x, acc[2 * k + 0]);
        acc[2 * k + 1] = fmaf(w, f.y, acc[2 * k + 1]);
    }
}

__global__ void __launch_bounds__(256)
aggregate_kernel(const float* __restrict__ X, float* __restrict__ out) {
    const int gw = (blockIdx.x * blockDim.x + threadIdx.x) >> 5;
    if (gw >= N_NODES) return;
    const int lane = threadIdx.x & 31;
    const int half = lane >> 4;                // even/odd edge stream
    const int hl   = lane & 15;                // 16B slot within the 256B row

    const int beg = g_off[gw];
    const int end = g_off[gw + 1];

    float acc[8];
    #pragma unroll
    for (int j = 0; j < 8; ++j) acc[j] = 0.f;

    int i = beg + half;
    for (; i + 2 < end; i += 4) {              // 2 edges per half per iter
        const unsigned v0 = __ldcs(&g_swp[i]);
        const unsigned v1 = __ldcs(&g_swp[i + 2]);
        const uint4 r0 = __ldg(
            reinterpret_cast<const uint4*>(g_Hh + (size_t)(v0 >> 15) * D) + hl);
        const uint4 r1 = __ldg(
            reinterpret_cast<const uint4*>(g_Hh + (size_t)(v1 >> 15) * D) + hl);
        fma_h8(acc, r0, unpack_w(v0));
        fma_h8(acc, r1, unpack_w(v1));
    }
    for (; i < end; i += 2) {
        const unsigned v = __ldcs(&g_swp[i]);
        const uint4 r = __ldg(
            reinterpret_cast<const uint4*>(g_Hh + (size_t)(v >> 15) * D) + hl);
        fma_h8(acc, r, unpack_w(v));
    }

    // Combine even/odd partials (same channel set per hl).
    #pragma unroll
    for (int j = 0; j < 8; ++j)
        acc[j] += __shfl_xor_sync(0xffffffffu, acc[j], 16);

    // Each lane writes one float4: channels hl*8 + half*4 .. +4.
    const int f4idx = hl * 2 + half;
    const float4 xv =
        __ldcs(reinterpret_cast<const float4*>(X + (size_t)gw * D) + f4idx);
    float4 o;
    o.x = fmaxf(acc[half * 4 + 0], 0.f) + xv.x;
    o.y = fmaxf(acc[half * 4 + 1], 0.f) + xv.y;
    o.z = fmaxf(acc[half * 4 + 2], 0.f) + xv.z;
    o.w = fmaxf(acc[half * 4 + 3], 0.f) + xv.w;
    __stcs(reinterpret_cast<float4*>(out + (size_t)gw * D) + f4idx, o);
}

// ===========================================================================
extern "C" void kernel_launch(void* const* d_in, const int* in_sizes, int n_in,
                              void* d_out, int out_size) {
    const float* X     = (const float*)d_in[0];
    const int*   esrc  = (const int*)d_in[1];
    const int*   edst  = (const int*)d_in[2];
    const float* ew    = (const float*)d_in[3];
    const float* gamma = (const float*)d_in[4];
    const float* beta  = (const float*)d_in[5];
    const float* W     = (const float*)d_in[6];
    const float* bias  = (const float*)d_in[7];
    float* out         = (float*)d_out;
    const int E        = in_sizes[1];

    cudaFuncSetAttribute(ln_linear_kernel,
                         cudaFuncAttributeMaxDynamicSharedMemorySize,
                         SMEM_BYTES);

    void* off_ptr = nullptr;
    cudaGetSymbolAddress(&off_ptr, g_off);

    const int n  = N_NODES + 1;
    const int nb = (n + 1023) / 1024;                 // 98

    // --- fork: CSR chain on side stream, GEMM on main stream ---------------
    cudaEventRecord(g_ctx.e_fork, 0);
    cudaStreamWaitEvent(g_ctx.s2, g_ctx.e_fork, 0);

    cudaMemsetAsync(off_ptr, 0, n * sizeof(int), g_ctx.s2);
    hist_rank_kernel<<<HIST_BLOCKS, 256, 0, g_ctx.s2>>>(edst, E);
    scan_chunk_kernel<<<nb, 1024, 0, g_ctx.s2>>>(n);
    scan_add_fused_kernel<<<nb, 1024, 0, g_ctx.s2>>>(n, nb);
    reorder_kernel<<<RORD_BLOCKS, 256, 0, g_ctx.s2>>>(esrc, edst, ew, E);
    cudaEventRecord(g_ctx.e_join, g_ctx.s2);

    ln_linear_kernel<<<(N_NODES + ROWS_PB - 1) / ROWS_PB, 256, SMEM_BYTES>>>(
        X, gamma, beta, W, bias);

    // --- join ------------------------------------------------------------
    cudaStreamWaitEvent(0, g_ctx.e_join, 0);
    aggregate_kernel<<<(N_NODES * 32 + 255) / 256, 256>>>(X, out);
}